// round 2
// baseline (speedup 1.0000x reference)
#include <cuda_runtime.h>
#include <math.h>

#define BZ   4
#define CH   64
#define HH   64
#define WW   64
#define LSEQ (HH*WW)      // 4096
#define NT   (BZ*LSEQ)    // 16384
#define DI   128
#define DS   16
#define DTR  4
#define GCH  64           // chunks per batch
#define TCH  (LSEQ/GCH)   // 64 steps per chunk

// ---------------- scratch (device globals; no allocation) ----------------
__device__ float g_seq[NT*CH];
__device__ float g_hn [NT*CH];
__device__ float g_xm [NT*DI];
__device__ float g_z  [NT*DI];
__device__ float g_xc [NT*DI];
__device__ float g_dt [NT*DI];
__device__ float g_dxc[NT*DI];
__device__ float g_Bm [NT*DS];
__device__ float g_Cm [NT*DS];
__device__ float g_yl [NT*DI];
__device__ float g_cd [NT*DI];
__device__ float g_E  [BZ*GCH*DI*DS];
__device__ float g_P  [BZ*GCH*DI*DS];
__device__ float g_H  [BZ*GCH*DI*DS];
__device__ float g_ys [NT*DI];
__device__ float g_A  [DI*DS];
__device__ int   g_chain[DI];

__device__ __forceinline__ float siluf(float v) { return v / (1.f + __expf(-v)); }

// ---------------- K0: A = -exp(A_log); detect integer-power structure ----
__global__ void k_initA(const float* __restrict__ A_log) {
    int d = threadIdx.x;
    float a0 = -expf(A_log[d*DS + 0]);
    int ok = 1;
    for (int s = 0; s < DS; ++s) {
        float a = -expf(A_log[d*DS + s]);
        g_A[d*DS + s] = a;
        if (fabsf(a - (float)(s+1)*a0) > 1e-3f*fabsf(a) + 1e-6f) ok = 0;
    }
    g_chain[d] = ok;
}

// ---------------- K1: axial DW conv + 1x1 conv + BN + ReLU + LN ----------
__global__ void k_stage1(const float* __restrict__ x,
                         const float* __restrict__ dwhw, const float* __restrict__ dwhb,
                         const float* __restrict__ dwww, const float* __restrict__ dwwb,
                         const float* __restrict__ convw, const float* __restrict__ convb,
                         const float* __restrict__ bng, const float* __restrict__ bnb,
                         const float* __restrict__ bnm, const float* __restrict__ bnv,
                         const float* __restrict__ lng, const float* __restrict__ lnb) {
    __shared__ __align__(16) float t[CH][68];
    __shared__ float r[CH][68];
    __shared__ float mu[WW], rs[WW];
    __shared__ float sc[CH], sh[CH];
    int blk = blockIdx.x;
    int b = blk / HH, h = blk % HH;
    int tid = threadIdx.x;

    if (tid < CH) {
        float s = bng[tid] * rsqrtf(bnv[tid] + 1e-5f);
        sc[tid] = s;
        sh[tid] = (convb[tid] - bnm[tid]) * s + bnb[tid];
    }
    const float* xb = x + (size_t)b*CH*LSEQ;
    for (int idx = tid; idx < CH*WW; idx += 256) {
        int c = idx >> 6, w = idx & 63;
        const float* xr = xb + c*LSEQ + h*WW;
        float xv = xr[w];
        float up = (h > 0)    ? xr[w - WW] : 0.f;
        float dn = (h < HH-1) ? xr[w + WW] : 0.f;
        float lf = (w > 0)    ? xr[w - 1]  : 0.f;
        float rt = (w < WW-1) ? xr[w + 1]  : 0.f;
        float v = xv
            + dwhw[c*3+0]*up + dwhw[c*3+1]*xv + dwhw[c*3+2]*dn + dwhb[c]
            + dwww[c*3+0]*lf + dwww[c*3+1]*xv + dwww[c*3+2]*rt + dwwb[c];
        t[c][w] = v;
    }
    __syncthreads();

    // 1x1 conv: 64 out x 64 pixels; thread = 4co x 4w microtile
    int cg = tid >> 4, tg = tid & 15;
    int co0 = cg * 4, w0 = tg * 4;
    float acc[4][4] = {};
    #pragma unroll 4
    for (int ci = 0; ci < CH; ++ci) {
        float4 av = *(const float4*)&t[ci][w0];
        float wv0 = __ldg(&convw[(co0+0)*CH + ci]);
        float wv1 = __ldg(&convw[(co0+1)*CH + ci]);
        float wv2 = __ldg(&convw[(co0+2)*CH + ci]);
        float wv3 = __ldg(&convw[(co0+3)*CH + ci]);
        acc[0][0] += wv0*av.x; acc[0][1] += wv0*av.y; acc[0][2] += wv0*av.z; acc[0][3] += wv0*av.w;
        acc[1][0] += wv1*av.x; acc[1][1] += wv1*av.y; acc[1][2] += wv1*av.z; acc[1][3] += wv1*av.w;
        acc[2][0] += wv2*av.x; acc[2][1] += wv2*av.y; acc[2][2] += wv2*av.z; acc[2][3] += wv2*av.w;
        acc[3][0] += wv3*av.x; acc[3][1] += wv3*av.y; acc[3][2] += wv3*av.z; acc[3][3] += wv3*av.w;
    }
    #pragma unroll
    for (int i = 0; i < 4; ++i)
        #pragma unroll
        for (int j = 0; j < 4; ++j) {
            float v = acc[i][j]*sc[co0+i] + sh[co0+i];
            r[co0+i][w0+j] = fmaxf(v, 0.f);
        }
    __syncthreads();

    if (tid < WW) {
        float m = 0.f;
        for (int c = 0; c < CH; ++c) m += r[c][tid];
        m *= (1.f/CH);
        float v = 0.f;
        for (int c = 0; c < CH; ++c) { float dd = r[c][tid] - m; v += dd*dd; }
        v *= (1.f/CH);
        mu[tid] = m; rs[tid] = rsqrtf(v + 1e-5f);
    }
    __syncthreads();

    int n0 = b*LSEQ + h*WW;
    for (int idx = tid; idx < CH*WW; idx += 256) {
        int w = idx >> 6, c = idx & 63;
        float rv = r[c][w];
        g_seq[(size_t)(n0+w)*CH + c] = rv;
        g_hn [(size_t)(n0+w)*CH + c] = (rv - mu[w]) * rs[w] * lng[c] + lnb[c];
    }
}

// ---------------- K2: in_proj GEMM [NT,64] x [256,64]^T -> xm,z ----------
__global__ void k_inproj(const float* __restrict__ W) {
    __shared__ __align__(16) float aT[CH][68];   // hn^T  [c][tok]
    __shared__ __align__(16) float wT[CH][68];   // W^T   [c][out-in-chunk] (reused as osm)
    int n0 = blockIdx.x * 64;
    int tid = threadIdx.x;
    for (int idx = tid; idx < 64*CH; idx += 256) {
        int tok = idx >> 6, c = idx & 63;
        aT[c][tok] = g_hn[(size_t)(n0+tok)*CH + c];
    }
    int cg = tid >> 4, tg = tid & 15;
    int oo0 = cg*4, t0 = tg*4;
    for (int chunk = 0; chunk < 4; ++chunk) {
        int o0 = chunk * 64;
        __syncthreads();
        for (int idx = tid; idx < 64*CH; idx += 256) {
            int dd = idx >> 6, c = idx & 63;
            wT[c][dd] = W[(o0+dd)*CH + c];
        }
        __syncthreads();
        float acc[4][4] = {};
        #pragma unroll 4
        for (int ci = 0; ci < CH; ++ci) {
            float4 av = *(const float4*)&aT[ci][t0];
            float4 wv = *(const float4*)&wT[ci][oo0];
            acc[0][0] += wv.x*av.x; acc[0][1] += wv.x*av.y; acc[0][2] += wv.x*av.z; acc[0][3] += wv.x*av.w;
            acc[1][0] += wv.y*av.x; acc[1][1] += wv.y*av.y; acc[1][2] += wv.y*av.z; acc[1][3] += wv.y*av.w;
            acc[2][0] += wv.z*av.x; acc[2][1] += wv.z*av.y; acc[2][2] += wv.z*av.z; acc[2][3] += wv.z*av.w;
            acc[3][0] += wv.w*av.x; acc[3][1] += wv.w*av.y; acc[3][2] += wv.w*av.z; acc[3][3] += wv.w*av.w;
        }
        __syncthreads();
        #pragma unroll
        for (int i = 0; i < 4; ++i)
            #pragma unroll
            for (int j = 0; j < 4; ++j) wT[oo0+i][t0+j] = acc[i][j];
        __syncthreads();
        for (int idx = tid; idx < 64*64; idx += 256) {
            int tok = idx >> 6, o = idx & 63;
            int dd = o0 + o;
            float v = wT[o][tok];
            int n = n0 + tok;
            if (dd < DI) g_xm[(size_t)n*DI + dd]      = v;
            else         g_z [(size_t)n*DI + dd - DI] = v;
        }
    }
}

// ---------------- K3: causal depthwise conv1d + SiLU ---------------------
__global__ void k_conv1d(const float* __restrict__ cw, const float* __restrict__ cb) {
    int idx = blockIdx.x * 256 + threadIdx.x;      // NT*DI threads
    int n = idx >> 7, d = idx & 127;
    int l = n & (LSEQ - 1);
    float acc = cb[d];
    #pragma unroll
    for (int k = 0; k < 4; ++k) {
        int ll = l - 3 + k;
        if (ll >= 0) acc += cw[d*4 + k] * g_xm[(size_t)(n - 3 + k)*DI + d];
    }
    g_xc[idx] = siluf(acc);
}

// ---------------- K4: x_proj + dt_proj + softplus -----------------------
__global__ void k_xproj(const float* __restrict__ xpw,
                        const float* __restrict__ dtpw,
                        const float* __restrict__ dtpb) {
    __shared__ __align__(16) float xcT[DI][68];    // [d][tok]
    __shared__ float dbc[64][40];                  // [tok][e]
    int n0 = blockIdx.x * 64;
    int tid = threadIdx.x;
    for (int idx = tid; idx < 64*DI; idx += 256) {
        int tok = idx >> 7, d = idx & 127;
        xcT[d][tok] = g_xc[(size_t)(n0+tok)*DI + d];
    }
    __syncthreads();
    int eg = tid >> 4, tg = tid & 15;
    if (eg < 9) {
        int e0 = eg*4, t0 = tg*4;
        float acc[4][4] = {};
        #pragma unroll 4
        for (int ci = 0; ci < DI; ++ci) {
            float4 av = *(const float4*)&xcT[ci][t0];
            float w0_ = __ldg(&xpw[(e0+0)*DI + ci]);
            float w1_ = __ldg(&xpw[(e0+1)*DI + ci]);
            float w2_ = __ldg(&xpw[(e0+2)*DI + ci]);
            float w3_ = __ldg(&xpw[(e0+3)*DI + ci]);
            acc[0][0] += w0_*av.x; acc[0][1] += w0_*av.y; acc[0][2] += w0_*av.z; acc[0][3] += w0_*av.w;
            acc[1][0] += w1_*av.x; acc[1][1] += w1_*av.y; acc[1][2] += w1_*av.z; acc[1][3] += w1_*av.w;
            acc[2][0] += w2_*av.x; acc[2][1] += w2_*av.y; acc[2][2] += w2_*av.z; acc[2][3] += w2_*av.w;
            acc[3][0] += w3_*av.x; acc[3][1] += w3_*av.y; acc[3][2] += w3_*av.z; acc[3][3] += w3_*av.w;
        }
        #pragma unroll
        for (int i = 0; i < 4; ++i)
            #pragma unroll
            for (int j = 0; j < 4; ++j) dbc[t0+j][e0+i] = acc[i][j];
    }
    __syncthreads();
    // dt = softplus(dbc[:,0:4] @ dtpw^T + dtpb); also dxc = dt * xc
    for (int idx = tid; idx < 64*DI; idx += 256) {
        int tok = idx >> 7, d = idx & 127;
        float raw = __ldg(&dtpb[d]);
        #pragma unroll
        for (int rr = 0; rr < DTR; ++rr) raw += dbc[tok][rr] * __ldg(&dtpw[d*DTR + rr]);
        float dt = (raw > 20.f) ? raw : log1pf(__expf(raw));
        size_t gi = (size_t)(n0+tok)*DI + d;
        g_dt [gi] = dt;
        g_dxc[gi] = dt * xcT[d][tok];
    }
    for (int idx = tid; idx < 64*DS; idx += 256) {
        int tok = idx >> 4, s = idx & 15;
        g_Bm[(size_t)(n0+tok)*DS + s] = dbc[tok][4 + s];
        g_Cm[(size_t)(n0+tok)*DS + s] = dbc[tok][20 + s];
    }
}

// ---------------- K5: pass 1 — local (zero-init) chunk scan --------------
__global__ void k_scan() {
    __shared__ float bcs[16][32];
    int blk = blockIdx.x;            // b*GCH + g
    int d = threadIdx.x;             // 128
    int n0 = blk * TCH;              // b*LSEQ + g*TCH
    float a0 = g_A[d*DS];
    bool chain = (g_chain[d] != 0);
    float As[DS];
    {
        const float4* ap = (const float4*)&g_A[d*DS];
        #pragma unroll
        for (int q = 0; q < 4; ++q) {
            float4 v = ap[q];
            As[q*4+0] = v.x; As[q*4+1] = v.y; As[q*4+2] = v.z; As[q*4+3] = v.w;
        }
    }
    float h[DS];
    #pragma unroll
    for (int s = 0; s < DS; ++s) h[s] = 0.f;
    float cd = 0.f;

    for (int tb = 0; tb < TCH; tb += 16) {
        __syncthreads();
        for (int idx = d; idx < 16*32; idx += 128) {
            int st = idx >> 5, j = idx & 31;
            bcs[st][j] = (j < 16) ? g_Bm[(size_t)(n0+tb+st)*DS + j]
                                  : g_Cm[(size_t)(n0+tb+st)*DS + (j-16)];
        }
        __syncthreads();
        if (chain) {
            #pragma unroll 4
            for (int st = 0; st < 16; ++st) {
                size_t gi = (size_t)(n0+tb+st)*DI + d;
                float dtv = g_dt[gi], dxv = g_dxc[gi];
                cd += dtv;
                float e1 = __expf(dtv * a0);
                float p = e1, y = 0.f;
                #pragma unroll
                for (int s = 0; s < DS; ++s) {
                    h[s] = p*h[s] + dxv*bcs[st][s];
                    y += h[s]*bcs[st][16+s];
                    p *= e1;
                }
                g_yl[gi] = y; g_cd[gi] = cd;
            }
        } else {
            for (int st = 0; st < 16; ++st) {
                size_t gi = (size_t)(n0+tb+st)*DI + d;
                float dtv = g_dt[gi], dxv = g_dxc[gi];
                cd += dtv;
                float y = 0.f;
                #pragma unroll
                for (int s = 0; s < DS; ++s) {
                    float dA = __expf(dtv * As[s]);
                    h[s] = dA*h[s] + dxv*bcs[st][s];
                    y += h[s]*bcs[st][16+s];
                }
                g_yl[gi] = y; g_cd[gi] = cd;
            }
        }
    }
    int base = blk*DI*DS + d*DS;
    if (chain) {
        float q = __expf(a0 * cd), p = q;
        #pragma unroll
        for (int s = 0; s < DS; ++s) { g_E[base+s] = h[s]; g_P[base+s] = p; p *= q; }
    } else {
        #pragma unroll
        for (int s = 0; s < DS; ++s) { g_E[base+s] = h[s]; g_P[base+s] = __expf(As[s]*cd); }
    }
}

// ---------------- K6: pass 2 — sequential chunk-state combine ------------
__global__ void k_comb() {
    int i = blockIdx.x * 256 + threadIdx.x;    // 8192 = BZ*DI*DS
    int b = i >> 11, r = i & 2047;
    float h = 0.f;
    for (int g = 0; g < GCH; ++g) {
        int idx = (b*GCH + g)*(DI*DS) + r;
        g_H[idx] = h;
        h = g_P[idx]*h + g_E[idx];
    }
}

// ---------------- K7: pass 3 — correction + gating -----------------------
__global__ void k_corr(const float* __restrict__ Dp) {
    __shared__ float Cs[4][DS];
    int tid = threadIdx.x;
    int d = tid & 127, tk = tid >> 7;
    int n0 = blockIdx.x * 4;
    int n = n0 + tk;
    int b = n / LSEQ, l = n % LSEQ, g = l / TCH;
    if (tid < 64) {
        int t_ = tid >> 4, s = tid & 15;
        Cs[t_][s] = g_Cm[(size_t)(n0+t_)*DS + s];
    }
    __syncthreads();
    float hv[DS];
    {
        const float4* Hp = (const float4*)&g_H[((size_t)(b*GCH + g)*DI + d)*DS];
        #pragma unroll
        for (int q = 0; q < 4; ++q) {
            float4 v = Hp[q];
            hv[q*4+0] = v.x; hv[q*4+1] = v.y; hv[q*4+2] = v.z; hv[q*4+3] = v.w;
        }
    }
    size_t gi = (size_t)n*DI + d;
    float cd = g_cd[gi];
    float a0 = g_A[d*DS];
    float y = g_yl[gi];
    if (g_chain[d]) {
        float q = __expf(a0 * cd), p = q;
        #pragma unroll
        for (int s = 0; s < DS; ++s) { y += Cs[tk][s]*p*hv[s]; p *= q; }
    } else {
        #pragma unroll
        for (int s = 0; s < DS; ++s) y += Cs[tk][s]*__expf(g_A[d*DS+s]*cd)*hv[s];
    }
    float xcv = g_xc[gi];
    float zv  = g_z[gi];
    g_ys[gi] = (y + xcv*Dp[d]) * siluf(zv);
}

// ---------------- K8: out_proj GEMM + residual + NCHW store --------------
__global__ void k_outproj(const float* __restrict__ Wout, float* __restrict__ out) {
    extern __shared__ __align__(16) float sm[];
    float (*ysT)[68]  = (float(*)[68])sm;                    // [128][68]
    float (*wT)[68]   = (float(*)[68])(sm + 128*68);         // [128][68], reused as osm
    float (*seqT)[68] = (float(*)[68])(sm + 2*128*68);       // [64][68]
    int n0 = blockIdx.x * 64;
    int tid = threadIdx.x;
    int b = n0 / LSEQ, l0 = n0 % LSEQ;
    for (int idx = tid; idx < 64*DI; idx += 256) {
        int tok = idx >> 7, d = idx & 127;
        ysT[d][tok] = g_ys[(size_t)(n0+tok)*DI + d];
    }
    for (int idx = tid; idx < DI*CH; idx += 256) {
        int d = idx & 127, c = idx >> 7;
        wT[d][c] = Wout[c*DI + d];
    }
    for (int idx = tid; idx < 64*CH; idx += 256) {
        int tok = idx >> 6, c = idx & 63;
        seqT[c][tok] = g_seq[(size_t)(n0+tok)*CH + c];
    }
    __syncthreads();
    int cg = tid >> 4, tg = tid & 15;
    int c0 = cg*4, t0 = tg*4;
    float acc[4][4] = {};
    #pragma unroll 4
    for (int d = 0; d < DI; ++d) {
        float4 av = *(const float4*)&ysT[d][t0];
        float4 wv = *(const float4*)&wT[d][c0];
        acc[0][0] += wv.x*av.x; acc[0][1] += wv.x*av.y; acc[0][2] += wv.x*av.z; acc[0][3] += wv.x*av.w;
        acc[1][0] += wv.y*av.x; acc[1][1] += wv.y*av.y; acc[1][2] += wv.y*av.z; acc[1][3] += wv.y*av.w;
        acc[2][0] += wv.z*av.x; acc[2][1] += wv.z*av.y; acc[2][2] += wv.z*av.z; acc[2][3] += wv.z*av.w;
        acc[3][0] += wv.w*av.x; acc[3][1] += wv.w*av.y; acc[3][2] += wv.w*av.z; acc[3][3] += wv.w*av.w;
    }
    #pragma unroll
    for (int i = 0; i < 4; ++i)
        #pragma unroll
        for (int j = 0; j < 4; ++j) acc[i][j] += seqT[c0+i][t0+j];
    __syncthreads();
    #pragma unroll
    for (int i = 0; i < 4; ++i)
        #pragma unroll
        for (int j = 0; j < 4; ++j) wT[c0+i][t0+j] = acc[i][j];
    __syncthreads();
    for (int idx = tid; idx < CH*64; idx += 256) {
        int c = idx >> 6, tok = idx & 63;
        out[((size_t)(b*CH + c))*LSEQ + l0 + tok] = wT[c][tok];
    }
}

// ---------------- launch --------------------------------------------------
extern "C" void kernel_launch(void* const* d_in, const int* in_sizes, int n_in,
                              void* d_out, int out_size) {
    const float* x       = (const float*)d_in[0];
    const float* dwh_w   = (const float*)d_in[1];
    const float* dwh_b   = (const float*)d_in[2];
    const float* dww_w   = (const float*)d_in[3];
    const float* dww_b   = (const float*)d_in[4];
    const float* conv_w  = (const float*)d_in[5];
    const float* conv_b  = (const float*)d_in[6];
    const float* bn_g    = (const float*)d_in[7];
    const float* bn_b    = (const float*)d_in[8];
    const float* bn_m    = (const float*)d_in[9];
    const float* bn_v    = (const float*)d_in[10];
    const float* ln_g    = (const float*)d_in[11];
    const float* ln_b    = (const float*)d_in[12];
    const float* in_proj = (const float*)d_in[13];
    const float* convd_w = (const float*)d_in[14];
    const float* convd_b = (const float*)d_in[15];
    const float* x_proj  = (const float*)d_in[16];
    const float* dt_w    = (const float*)d_in[17];
    const float* dt_b    = (const float*)d_in[18];
    const float* A_log   = (const float*)d_in[19];
    const float* Dp      = (const float*)d_in[20];
    const float* out_w   = (const float*)d_in[21];
    float* out = (float*)d_out;

    cudaFuncSetAttribute(k_outproj, cudaFuncAttributeMaxDynamicSharedMemorySize, 87040);

    k_initA<<<1, DI>>>(A_log);
    k_stage1<<<BZ*HH, 256>>>(x, dwh_w, dwh_b, dww_w, dww_b, conv_w, conv_b,
                             bn_g, bn_b, bn_m, bn_v, ln_g, ln_b);
    k_inproj<<<NT/64, 256>>>(in_proj);
    k_conv1d<<<(NT*DI)/256, 256>>>(convd_w, convd_b);
    k_xproj<<<NT/64, 256>>>(x_proj, dt_w, dt_b);
    k_scan<<<BZ*GCH, DI>>>();
    k_comb<<<32, 256>>>();
    k_corr<<<NT/4, 512>>>(Dp);
    k_outproj<<<NT/64, 256, 87040>>>(out_w, out);
}

// round 7
// speedup vs baseline: 1.5465x; 1.5465x over previous
#include <cuda_runtime.h>
#include <math.h>

#define BZ   4
#define CH   64
#define HH   64
#define WW   64
#define LSEQ (HH*WW)      // 4096
#define NT   (BZ*LSEQ)    // 16384
#define DI   128
#define DS   16
#define DTR  4
#define GCH  64           // chunks per batch
#define TCH  (LSEQ/GCH)   // 64 steps per chunk

// ---------------- scratch (device globals; no allocation) ----------------
__device__ float g_seq[NT*CH];
__device__ float g_xm [NT*DI];
__device__ float g_z  [NT*DI];
__device__ float g_xc [NT*DI];
__device__ float g_Cm [NT*DS];
__device__ float g_yl [NT*DI];
__device__ float g_cd [NT*DI];
__device__ float g_E  [BZ*GCH*DI*DS];
__device__ float g_P  [BZ*GCH*DI*DS];
__device__ float g_H  [BZ*GCH*DI*DS];
__device__ float g_A  [DI*DS];
__device__ int   g_chain[DI];

__device__ __forceinline__ float siluf(float v) { return v / (1.f + __expf(-v)); }

// ---------------- K0: A = -exp(A_log); detect integer-power structure ----
__global__ void k_initA(const float* __restrict__ A_log) {
    int d = threadIdx.x;
    float a0 = -expf(A_log[d*DS + 0]);
    int ok = 1;
    for (int s = 0; s < DS; ++s) {
        float a = -expf(A_log[d*DS + s]);
        g_A[d*DS + s] = a;
        if (fabsf(a - (float)(s+1)*a0) > 1e-3f*fabsf(a) + 1e-6f) ok = 0;
    }
    g_chain[d] = ok;
}

// ======== K1: axial DW + 1x1 conv + BN + ReLU + LN + in_proj GEMM ========
__global__ __launch_bounds__(256) void k_fuse1(
        const float* __restrict__ x,
        const float* __restrict__ dwhw, const float* __restrict__ dwhb,
        const float* __restrict__ dwww, const float* __restrict__ dwwb,
        const float* __restrict__ convw, const float* __restrict__ convb,
        const float* __restrict__ bng, const float* __restrict__ bnb,
        const float* __restrict__ bnm, const float* __restrict__ bnv,
        const float* __restrict__ lng, const float* __restrict__ lnb,
        const float* __restrict__ Win) {
    __shared__ __align__(16) float t[CH][68];   // conv tmp, later W tile / out stage
    __shared__ __align__(16) float r[CH][68];   // seq / hn  [c][tok]
    __shared__ float mu[WW], rs[WW];
    __shared__ float sc[CH], sh[CH];
    int blk = blockIdx.x;
    int b = blk >> 6, h = blk & 63;
    int tid = threadIdx.x;

    if (tid < CH) {
        float s = bng[tid] * rsqrtf(bnv[tid] + 1e-5f);
        sc[tid] = s;
        sh[tid] = (convb[tid] - bnm[tid]) * s + bnb[tid];
    }
    const float* xb = x + (size_t)b*CH*LSEQ;
    for (int idx = tid; idx < CH*WW; idx += 256) {
        int c = idx >> 6, w = idx & 63;
        const float* xr = xb + c*LSEQ + h*WW;
        float xv = xr[w];
        float up = (h > 0)    ? xr[w - WW] : 0.f;
        float dn = (h < HH-1) ? xr[w + WW] : 0.f;
        float lf = (w > 0)    ? xr[w - 1]  : 0.f;
        float rt = (w < WW-1) ? xr[w + 1]  : 0.f;
        float v = xv
            + dwhw[c*3+0]*up + dwhw[c*3+1]*xv + dwhw[c*3+2]*dn + dwhb[c]
            + dwww[c*3+0]*lf + dwww[c*3+1]*xv + dwww[c*3+2]*rt + dwwb[c];
        t[c][w] = v;
    }
    __syncthreads();

    // 1x1 conv (64x64x64) -> BN -> ReLU into r
    int cg = tid >> 4, tg = tid & 15;
    int co0 = cg * 4, w0 = tg * 4;
    {
        float acc[4][4] = {};
        #pragma unroll 4
        for (int ci = 0; ci < CH; ++ci) {
            float4 av = *(const float4*)&t[ci][w0];
            float wv0 = __ldg(&convw[(co0+0)*CH + ci]);
            float wv1 = __ldg(&convw[(co0+1)*CH + ci]);
            float wv2 = __ldg(&convw[(co0+2)*CH + ci]);
            float wv3 = __ldg(&convw[(co0+3)*CH + ci]);
            acc[0][0] += wv0*av.x; acc[0][1] += wv0*av.y; acc[0][2] += wv0*av.z; acc[0][3] += wv0*av.w;
            acc[1][0] += wv1*av.x; acc[1][1] += wv1*av.y; acc[1][2] += wv1*av.z; acc[1][3] += wv1*av.w;
            acc[2][0] += wv2*av.x; acc[2][1] += wv2*av.y; acc[2][2] += wv2*av.z; acc[2][3] += wv2*av.w;
            acc[3][0] += wv3*av.x; acc[3][1] += wv3*av.y; acc[3][2] += wv3*av.z; acc[3][3] += wv3*av.w;
        }
        #pragma unroll
        for (int i = 0; i < 4; ++i)
            #pragma unroll
            for (int j = 0; j < 4; ++j) {
                float v = acc[i][j]*sc[co0+i] + sh[co0+i];
                r[co0+i][w0+j] = fmaxf(v, 0.f);
            }
    }
    __syncthreads();

    if (tid < WW) {
        float m = 0.f;
        for (int c = 0; c < CH; ++c) m += r[c][tid];
        m *= (1.f/CH);
        float v = 0.f;
        for (int c = 0; c < CH; ++c) { float dd = r[c][tid] - m; v += dd*dd; }
        v *= (1.f/CH);
        mu[tid] = m; rs[tid] = rsqrtf(v + 1e-5f);
    }
    __syncthreads();

    int n0 = b*LSEQ + h*WW;
    // store seq; normalize r in place -> hn[c][tok]
    for (int idx = tid; idx < CH*WW; idx += 256) {
        int w = idx >> 6, c = idx & 63;
        float rv = r[c][w];
        g_seq[(size_t)(n0+w)*CH + c] = rv;
        r[c][w] = (rv - mu[w]) * rs[w] * lng[c] + lnb[c];
    }

    // in_proj GEMM: hn[64tok x 64c] x Win[256 x 64]^T
    int oo0 = cg*4, t0 = tg*4;
    for (int chunk = 0; chunk < 4; ++chunk) {
        int o0 = chunk * 64;
        __syncthreads();
        for (int idx = tid; idx < 64*CH; idx += 256) {
            int dd = idx >> 6, c = idx & 63;
            t[c][dd] = Win[(o0+dd)*CH + c];
        }
        __syncthreads();
        float acc[4][4] = {};
        #pragma unroll 4
        for (int ci = 0; ci < CH; ++ci) {
            float4 av = *(const float4*)&r[ci][t0];
            float4 wv = *(const float4*)&t[ci][oo0];
            acc[0][0] += wv.x*av.x; acc[0][1] += wv.x*av.y; acc[0][2] += wv.x*av.z; acc[0][3] += wv.x*av.w;
            acc[1][0] += wv.y*av.x; acc[1][1] += wv.y*av.y; acc[1][2] += wv.y*av.z; acc[1][3] += wv.y*av.w;
            acc[2][0] += wv.z*av.x; acc[2][1] += wv.z*av.y; acc[2][2] += wv.z*av.z; acc[2][3] += wv.z*av.w;
            acc[3][0] += wv.w*av.x; acc[3][1] += wv.w*av.y; acc[3][2] += wv.w*av.z; acc[3][3] += wv.w*av.w;
        }
        __syncthreads();
        #pragma unroll
        for (int i = 0; i < 4; ++i)
            #pragma unroll
            for (int j = 0; j < 4; ++j) t[oo0+i][t0+j] = acc[i][j];
        __syncthreads();
        for (int idx = tid; idx < 64*64; idx += 256) {
            int tok = idx >> 6, o = idx & 63;
            int dd = o0 + o;
            float v = t[o][tok];
            int n = n0 + tok;
            if (dd < DI) g_xm[(size_t)n*DI + dd]      = v;
            else         g_z [(size_t)n*DI + dd - DI] = v;
        }
    }
}

// ======== K2: conv1d+SiLU + x_proj + dt + local chunk scan ===============
// dyn smem: xmS[67][132] | xcS[64][129] | dbc[64][40]
#define XM_PITCH 132
#define XC_PITCH 129
__global__ __launch_bounds__(256) void k_fuse2(
        const float* __restrict__ cw, const float* __restrict__ cb,
        const float* __restrict__ xpw,
        const float* __restrict__ dtpw, const float* __restrict__ dtpb) {
    extern __shared__ __align__(16) float sm[];
    float* xmS = sm;                      // 67*132 = 8844 (later reused: dt rows 0..63, then E/P staging)
    float* xcS = sm + 8844;               // 64*129 = 8256
    float* dbc = sm + 8844 + 8256;        // 64*40  = 2560
    int blk = blockIdx.x;                 // b*64 + g
    int g = blk & 63;
    int tid = threadIdx.x;
    int n0 = blk * TCH;

    // phase A: load xm tile with 3-token halo, compute xc = silu(conv1d)
    for (int idx = tid; idx < 67*DI; idx += 256) {
        int i = idx >> 7, d = idx & 127;
        float v = 0.f;
        if (g > 0 || i >= 3) v = g_xm[(size_t)(n0 - 3 + i)*DI + d];
        xmS[i*XM_PITCH + d] = v;
    }
    __syncthreads();
    for (int idx = tid; idx < 64*DI; idx += 256) {
        int tok = idx >> 7, d = idx & 127;
        float acc = __ldg(&cb[d]);
        #pragma unroll
        for (int k = 0; k < 4; ++k)
            acc += __ldg(&cw[d*4 + k]) * xmS[(tok + k)*XM_PITCH + d];
        float v = siluf(acc);
        xcS[tok*XC_PITCH + d] = v;
        g_xc[(size_t)(n0+tok)*DI + d] = v;
    }
    __syncthreads();

    // phase B: dbc = xc @ xpw^T   (36 outs x 64 toks x 128 K)
    int eg = tid >> 4, tg = tid & 15;
    if (eg < 9) {
        int e0 = eg*4, t0 = tg*4;
        float acc[4][4] = {};
        #pragma unroll 4
        for (int ci = 0; ci < DI; ++ci) {
            float w0_ = __ldg(&xpw[(e0+0)*DI + ci]);
            float w1_ = __ldg(&xpw[(e0+1)*DI + ci]);
            float w2_ = __ldg(&xpw[(e0+2)*DI + ci]);
            float w3_ = __ldg(&xpw[(e0+3)*DI + ci]);
            float a0_ = xcS[(t0+0)*XC_PITCH + ci];
            float a1_ = xcS[(t0+1)*XC_PITCH + ci];
            float a2_ = xcS[(t0+2)*XC_PITCH + ci];
            float a3_ = xcS[(t0+3)*XC_PITCH + ci];
            acc[0][0] += w0_*a0_; acc[0][1] += w0_*a1_; acc[0][2] += w0_*a2_; acc[0][3] += w0_*a3_;
            acc[1][0] += w1_*a0_; acc[1][1] += w1_*a1_; acc[1][2] += w1_*a2_; acc[1][3] += w1_*a3_;
            acc[2][0] += w2_*a0_; acc[2][1] += w2_*a1_; acc[2][2] += w2_*a2_; acc[2][3] += w2_*a3_;
            acc[3][0] += w3_*a0_; acc[3][1] += w3_*a1_; acc[3][2] += w3_*a2_; acc[3][3] += w3_*a3_;
        }
        #pragma unroll
        for (int i = 0; i < 4; ++i)
            #pragma unroll
            for (int j = 0; j < 4; ++j) dbc[(t0+j)*40 + e0+i] = acc[i][j];
    }
    __syncthreads();

    // phase C: dt = softplus(dbc[:,0:4] @ dtpw^T + b) -> overwrite xmS rows 0..63
    for (int idx = tid; idx < 64*DI; idx += 256) {
        int tok = idx >> 7, d = idx & 127;
        float raw = __ldg(&dtpb[d]);
        #pragma unroll
        for (int rr = 0; rr < DTR; ++rr) raw += dbc[tok*40 + rr] * __ldg(&dtpw[d*DTR + rr]);
        float dt = (raw > 20.f) ? raw : log1pf(__expf(raw));
        xmS[tok*XM_PITCH + d] = dt;
    }
    // export C for K4
    for (int idx = tid; idx < 64*DS; idx += 256) {
        int tok = idx >> 4, s = idx & 15;
        g_Cm[(size_t)(n0+tok)*DS + s] = dbc[tok*40 + 20 + s];
    }
    __syncthreads();

    // phase D: local scan (zero-init), threads 0..127 = d
    float hreg[DS];
    float cd = 0.f;
    int d = tid;
    if (d < DI) {
        float a0 = g_A[d*DS];
        bool chain = (g_chain[d] != 0);
        float As[DS];
        #pragma unroll
        for (int s = 0; s < DS; ++s) As[s] = g_A[d*DS + s];
        #pragma unroll
        for (int s = 0; s < DS; ++s) hreg[s] = 0.f;

        if (chain) {
            for (int st = 0; st < TCH; ++st) {
                float dtv = xmS[st*XM_PITCH + d];
                float xcv = xcS[st*XC_PITCH + d];
                float dxv = dtv * xcv;
                cd += dtv;
                float e1 = __expf(dtv * a0);
                float e2 = e1*e1, e3 = e2*e1, e4 = e2*e2;
                float pe0 = e1, pe1 = e2, pe2 = e3, pe3 = e4;
                float base = 1.f;
                float y = 0.f;
                #pragma unroll
                for (int gq = 0; gq < 4; ++gq) {
                    int s0 = gq*4;
                    float p0 = base*pe0, p1 = base*pe1, p2 = base*pe2, p3 = base*pe3;
                    hreg[s0+0] = p0*hreg[s0+0] + dxv*dbc[st*40 + 4 + s0+0];
                    hreg[s0+1] = p1*hreg[s0+1] + dxv*dbc[st*40 + 4 + s0+1];
                    hreg[s0+2] = p2*hreg[s0+2] + dxv*dbc[st*40 + 4 + s0+2];
                    hreg[s0+3] = p3*hreg[s0+3] + dxv*dbc[st*40 + 4 + s0+3];
                    y += hreg[s0+0]*dbc[st*40 + 20 + s0+0];
                    y += hreg[s0+1]*dbc[st*40 + 20 + s0+1];
                    y += hreg[s0+2]*dbc[st*40 + 20 + s0+2];
                    y += hreg[s0+3]*dbc[st*40 + 20 + s0+3];
                    base *= e4;
                }
                size_t gi = (size_t)(n0+st)*DI + d;
                g_yl[gi] = y; g_cd[gi] = cd;
            }
        } else {
            for (int st = 0; st < TCH; ++st) {
                float dtv = xmS[st*XM_PITCH + d];
                float xcv = xcS[st*XC_PITCH + d];
                float dxv = dtv * xcv;
                cd += dtv;
                float y = 0.f;
                #pragma unroll
                for (int s = 0; s < DS; ++s) {
                    float dA = __expf(dtv * As[s]);
                    hreg[s] = dA*hreg[s] + dxv*dbc[st*40 + 4 + s];
                    y += hreg[s]*dbc[st*40 + 20 + s];
                }
                size_t gi = (size_t)(n0+st)*DI + d;
                g_yl[gi] = y; g_cd[gi] = cd;
            }
        }
    }
    __syncthreads();   // all dt reads done before staging overwrites xmS
    if (d < DI) {
        float* stgE = xmS;          // 2048 floats
        float* stgP = xmS + 2048;   // 2048 floats
        float a0 = g_A[d*DS];
        bool chain = (g_chain[d] != 0);
        #pragma unroll
        for (int s = 0; s < DS; ++s) stgE[d*DS + s] = hreg[s];
        if (chain) {
            float q = __expf(a0 * cd);
            float q2 = q*q, q3 = q2*q, q4 = q2*q2;
            float base = 1.f;
            #pragma unroll
            for (int gq = 0; gq < 4; ++gq) {
                stgP[d*DS + gq*4+0] = base*q;
                stgP[d*DS + gq*4+1] = base*q2;
                stgP[d*DS + gq*4+2] = base*q3;
                stgP[d*DS + gq*4+3] = base*q4;
                base *= q4;
            }
        } else {
            #pragma unroll
            for (int s = 0; s < DS; ++s) stgP[d*DS + s] = __expf(g_A[d*DS+s]*cd);
        }
    }
    __syncthreads();
    for (int idx = tid; idx < DI*DS; idx += 256) {
        g_E[(size_t)blk*DI*DS + idx] = xmS[idx];
        g_P[(size_t)blk*DI*DS + idx] = xmS[2048 + idx];
    }
}

// ---------------- K3: sequential chunk-state combine ---------------------
__global__ void k_comb() {
    int i = blockIdx.x * 256 + threadIdx.x;    // 8192 = BZ*DI*DS
    int b = i >> 11, r = i & 2047;
    float h = 0.f;
    for (int g = 0; g < GCH; ++g) {
        int idx = (b*GCH + g)*(DI*DS) + r;
        g_H[idx] = h;
        h = g_P[idx]*h + g_E[idx];
    }
}

// ======== K4: correction + gating + out_proj + residual + NCHW ===========
// dyn smem: ysT[128][68] | wT[128][68] | seqT[64][68] | Hs[128][17] | Cs[64][16] | a0s|dps|chs
__global__ __launch_bounds__(256) void k_fuse4(const float* __restrict__ Dp,
                                               const float* __restrict__ Wout,
                                               float* __restrict__ out) {
    extern __shared__ __align__(16) float sm[];
    float* ysT  = sm;                    // [128][68]
    float* wT   = sm + 8704;             // [128][68]
    float* seqT = sm + 17408;            // [64][68]
    float* Hs   = sm + 21760;            // [128][17]
    float* Cs   = sm + 23936;            // [64][16]
    float* a0s  = sm + 24960;            // [128]
    float* dps  = sm + 25088;            // [128]
    float* chs  = sm + 25216;            // [128]
    int blk = blockIdx.x;                // b*64 + g
    int b = blk >> 6, g = blk & 63;
    int n0 = blk * 64;
    int l0 = g * 64;
    int tid = threadIdx.x;

    for (int idx = tid; idx < DI*DS; idx += 256)
        Hs[(idx >> 4)*17 + (idx & 15)] = g_H[(size_t)blk*DI*DS + idx];
    for (int idx = tid; idx < 64*DS; idx += 256)
        Cs[idx] = g_Cm[(size_t)n0*DS + idx];
    if (tid < DI) {
        a0s[tid] = g_A[tid*DS];
        dps[tid] = Dp[tid];
        chs[tid] = (float)g_chain[tid];
    }
    for (int idx = tid; idx < DI*CH; idx += 256) {
        int d = idx & 127, c = idx >> 7;
        wT[d*68 + c] = Wout[c*DI + d];
    }
    for (int idx = tid; idx < 64*CH; idx += 256) {
        int tok = idx >> 6, c = idx & 63;
        seqT[c*68 + tok] = g_seq[(size_t)(n0+tok)*CH + c];
    }
    __syncthreads();

    // correction + gating -> ysT[d][tok]
    for (int idx = tid; idx < 64*DI; idx += 256) {
        int tok = idx >> 7, d = idx & 127;
        size_t gi = (size_t)(n0+tok)*DI + d;
        float cdv = g_cd[gi];
        float y   = g_yl[gi];
        float xcv = g_xc[gi];
        float zv  = g_z[gi];
        if (chs[d] != 0.f) {
            float q = __expf(a0s[d] * cdv);
            float poly = Cs[tok*16 + 15] * Hs[d*17 + 15];
            #pragma unroll
            for (int s = 14; s >= 0; --s)
                poly = fmaf(q, poly, Cs[tok*16 + s] * Hs[d*17 + s]);
            y += q * poly;
        } else {
            #pragma unroll
            for (int s = 0; s < DS; ++s)
                y += Cs[tok*16 + s] * __expf(g_A[d*DS + s]*cdv) * Hs[d*17 + s];
        }
        ysT[d*68 + tok] = (y + xcv*dps[d]) * siluf(zv);
    }
    __syncthreads();

    // out_proj GEMM [64c x 64tok x 128K] + residual
    int cg = tid >> 4, tg = tid & 15;
    int c0 = cg*4, t0 = tg*4;
    float acc[4][4] = {};
    #pragma unroll 4
    for (int d = 0; d < DI; ++d) {
        float4 av = *(const float4*)&ysT[d*68 + t0];
        float4 wv = *(const float4*)&wT[d*68 + c0];
        acc[0][0] += wv.x*av.x; acc[0][1] += wv.x*av.y; acc[0][2] += wv.x*av.z; acc[0][3] += wv.x*av.w;
        acc[1][0] += wv.y*av.x; acc[1][1] += wv.y*av.y; acc[1][2] += wv.y*av.z; acc[1][3] += wv.y*av.w;
        acc[2][0] += wv.z*av.x; acc[2][1] += wv.z*av.y; acc[2][2] += wv.z*av.z; acc[2][3] += wv.z*av.w;
        acc[3][0] += wv.w*av.x; acc[3][1] += wv.w*av.y; acc[3][2] += wv.w*av.z; acc[3][3] += wv.w*av.w;
    }
    #pragma unroll
    for (int i = 0; i < 4; ++i)
        #pragma unroll
        for (int j = 0; j < 4; ++j) acc[i][j] += seqT[(c0+i)*68 + t0+j];
    __syncthreads();
    #pragma unroll
    for (int i = 0; i < 4; ++i)
        #pragma unroll
        for (int j = 0; j < 4; ++j) wT[(c0+i)*68 + t0+j] = acc[i][j];
    __syncthreads();
    for (int idx = tid; idx < CH*64; idx += 256) {
        int c = idx >> 6, tok = idx & 63;
        out[((size_t)(b*CH + c))*LSEQ + l0 + tok] = wT[c*68 + tok];
    }
}

// ---------------- launch --------------------------------------------------
extern "C" void kernel_launch(void* const* d_in, const int* in_sizes, int n_in,
                              void* d_out, int out_size) {
    const float* x       = (const float*)d_in[0];
    const float* dwh_w   = (const float*)d_in[1];
    const float* dwh_b   = (const float*)d_in[2];
    const float* dww_w   = (const float*)d_in[3];
    const float* dww_b   = (const float*)d_in[4];
    const float* conv_w  = (const float*)d_in[5];
    const float* conv_b  = (const float*)d_in[6];
    const float* bn_g    = (const float*)d_in[7];
    const float* bn_b    = (const float*)d_in[8];
    const float* bn_m    = (const float*)d_in[9];
    const float* bn_v    = (const float*)d_in[10];
    const float* ln_g    = (const float*)d_in[11];
    const float* ln_b    = (const float*)d_in[12];
    const float* in_proj = (const float*)d_in[13];
    const float* convd_w = (const float*)d_in[14];
    const float* convd_b = (const float*)d_in[15];
    const float* x_proj  = (const float*)d_in[16];
    const float* dt_w    = (const float*)d_in[17];
    const float* dt_b    = (const float*)d_in[18];
    const float* A_log   = (const float*)d_in[19];
    const float* Dp      = (const float*)d_in[20];
    const float* out_w   = (const float*)d_in[21];
    float* out = (float*)d_out;

    static int done = 0;
    // (attribute setting is idempotent and not a stream op; safe under capture)
    cudaFuncSetAttribute(k_fuse2, cudaFuncAttributeMaxDynamicSharedMemorySize, 78640);
    cudaFuncSetAttribute(k_fuse4, cudaFuncAttributeMaxDynamicSharedMemorySize, 101376);
    (void)done;

    k_initA<<<1, DI>>>(A_log);
    k_fuse1<<<BZ*HH, 256>>>(x, dwh_w, dwh_b, dww_w, dww_b, conv_w, conv_b,
                            bn_g, bn_b, bn_m, bn_v, ln_g, ln_b, in_proj);
    k_fuse2<<<BZ*GCH, 256, 78640>>>(convd_w, convd_b, x_proj, dt_w, dt_b);
    k_comb<<<32, 256>>>();
    k_fuse4<<<BZ*GCH, 256, 101376>>>(Dp, out_w, out);
}

// round 8
// speedup vs baseline: 1.7551x; 1.1349x over previous
#include <cuda_runtime.h>
#include <math.h>

#define BZ   4
#define CH   64
#define HH   64
#define WW   64
#define LSEQ (HH*WW)      // 4096
#define NT   (BZ*LSEQ)    // 16384
#define DI   128
#define DS   16
#define DTR  4
#define GCH  64           // chunks per batch
#define TCH  (LSEQ/GCH)   // 64 steps per chunk

// ---------------- scratch (device globals; no allocation) ----------------
__device__ float g_seq[NT*CH];
__device__ float g_xm [NT*DI];
__device__ float g_z  [NT*DI];
__device__ float g_xc [NT*DI];
__device__ float g_Cm [NT*DS];
__device__ float g_yl [NT*DI];
__device__ float g_cd [NT*DI];
__device__ float g_E  [BZ*GCH*DI*DS];
__device__ float g_P  [BZ*GCH*DI*DS];
__device__ float g_H  [BZ*GCH*DI*DS];
__device__ float g_A  [DI*DS];
__device__ int   g_chain[DI];

__device__ __forceinline__ float siluf(float v) { return v / (1.f + __expf(-v)); }

// ---------------- K0: A = -exp(A_log); detect integer-power structure ----
__global__ void k_initA(const float* __restrict__ A_log) {
    int d = threadIdx.x;
    float a0 = -expf(A_log[d*DS + 0]);
    int ok = 1;
    for (int s = 0; s < DS; ++s) {
        float a = -expf(A_log[d*DS + s]);
        g_A[d*DS + s] = a;
        if (fabsf(a - (float)(s+1)*a0) > 1e-3f*fabsf(a) + 1e-6f) ok = 0;
    }
    g_chain[d] = ok;
}

// ======== K1: axial DW + 1x1 conv + BN + ReLU + LN + in_proj GEMM ========
__global__ __launch_bounds__(256) void k_fuse1(
        const float* __restrict__ x,
        const float* __restrict__ dwhw, const float* __restrict__ dwhb,
        const float* __restrict__ dwww, const float* __restrict__ dwwb,
        const float* __restrict__ convw, const float* __restrict__ convb,
        const float* __restrict__ bng, const float* __restrict__ bnb,
        const float* __restrict__ bnm, const float* __restrict__ bnv,
        const float* __restrict__ lng, const float* __restrict__ lnb,
        const float* __restrict__ Win) {
    __shared__ __align__(16) float t[CH][68];   // conv tmp, later W tile / out stage
    __shared__ __align__(16) float r[CH][68];   // seq / hn  [c][tok]
    __shared__ float mu[WW], rs[WW];
    __shared__ float sc[CH], sh[CH];
    int blk = blockIdx.x;
    int b = blk >> 6, h = blk & 63;
    int tid = threadIdx.x;

    if (tid < CH) {
        float s = bng[tid] * rsqrtf(bnv[tid] + 1e-5f);
        sc[tid] = s;
        sh[tid] = (convb[tid] - bnm[tid]) * s + bnb[tid];
    }
    const float* xb = x + (size_t)b*CH*LSEQ;
    for (int idx = tid; idx < CH*WW; idx += 256) {
        int c = idx >> 6, w = idx & 63;
        const float* xr = xb + c*LSEQ + h*WW;
        float xv = xr[w];
        float up = (h > 0)    ? xr[w - WW] : 0.f;
        float dn = (h < HH-1) ? xr[w + WW] : 0.f;
        float lf = (w > 0)    ? xr[w - 1]  : 0.f;
        float rt = (w < WW-1) ? xr[w + 1]  : 0.f;
        float v = xv
            + dwhw[c*3+0]*up + dwhw[c*3+1]*xv + dwhw[c*3+2]*dn + dwhb[c]
            + dwww[c*3+0]*lf + dwww[c*3+1]*xv + dwww[c*3+2]*rt + dwwb[c];
        t[c][w] = v;
    }
    __syncthreads();

    // 1x1 conv (64x64x64) -> BN -> ReLU into r
    int cg = tid >> 4, tg = tid & 15;
    int co0 = cg * 4, w0 = tg * 4;
    {
        float acc[4][4] = {};
        #pragma unroll 4
        for (int ci = 0; ci < CH; ++ci) {
            float4 av = *(const float4*)&t[ci][w0];
            float wv0 = __ldg(&convw[(co0+0)*CH + ci]);
            float wv1 = __ldg(&convw[(co0+1)*CH + ci]);
            float wv2 = __ldg(&convw[(co0+2)*CH + ci]);
            float wv3 = __ldg(&convw[(co0+3)*CH + ci]);
            acc[0][0] += wv0*av.x; acc[0][1] += wv0*av.y; acc[0][2] += wv0*av.z; acc[0][3] += wv0*av.w;
            acc[1][0] += wv1*av.x; acc[1][1] += wv1*av.y; acc[1][2] += wv1*av.z; acc[1][3] += wv1*av.w;
            acc[2][0] += wv2*av.x; acc[2][1] += wv2*av.y; acc[2][2] += wv2*av.z; acc[2][3] += wv2*av.w;
            acc[3][0] += wv3*av.x; acc[3][1] += wv3*av.y; acc[3][2] += wv3*av.z; acc[3][3] += wv3*av.w;
        }
        #pragma unroll
        for (int i = 0; i < 4; ++i)
            #pragma unroll
            for (int j = 0; j < 4; ++j) {
                float v = acc[i][j]*sc[co0+i] + sh[co0+i];
                r[co0+i][w0+j] = fmaxf(v, 0.f);
            }
    }
    __syncthreads();

    if (tid < WW) {
        float m = 0.f;
        for (int c = 0; c < CH; ++c) m += r[c][tid];
        m *= (1.f/CH);
        float v = 0.f;
        for (int c = 0; c < CH; ++c) { float dd = r[c][tid] - m; v += dd*dd; }
        v *= (1.f/CH);
        mu[tid] = m; rs[tid] = rsqrtf(v + 1e-5f);
    }
    __syncthreads();

    int n0 = b*LSEQ + h*WW;
    // store seq; normalize r in place -> hn[c][tok]
    for (int idx = tid; idx < CH*WW; idx += 256) {
        int w = idx >> 6, c = idx & 63;
        float rv = r[c][w];
        g_seq[(size_t)(n0+w)*CH + c] = rv;
        r[c][w] = (rv - mu[w]) * rs[w] * lng[c] + lnb[c];
    }

    // in_proj GEMM: hn[64tok x 64c] x Win[256 x 64]^T
    int oo0 = cg*4, t0 = tg*4;
    for (int chunk = 0; chunk < 4; ++chunk) {
        int o0 = chunk * 64;
        __syncthreads();
        for (int idx = tid; idx < 64*CH; idx += 256) {
            int dd = idx >> 6, c = idx & 63;
            t[c][dd] = Win[(o0+dd)*CH + c];
        }
        __syncthreads();
        float acc[4][4] = {};
        #pragma unroll 4
        for (int ci = 0; ci < CH; ++ci) {
            float4 av = *(const float4*)&r[ci][t0];
            float4 wv = *(const float4*)&t[ci][oo0];
            acc[0][0] += wv.x*av.x; acc[0][1] += wv.x*av.y; acc[0][2] += wv.x*av.z; acc[0][3] += wv.x*av.w;
            acc[1][0] += wv.y*av.x; acc[1][1] += wv.y*av.y; acc[1][2] += wv.y*av.z; acc[1][3] += wv.y*av.w;
            acc[2][0] += wv.z*av.x; acc[2][1] += wv.z*av.y; acc[2][2] += wv.z*av.z; acc[2][3] += wv.z*av.w;
            acc[3][0] += wv.w*av.x; acc[3][1] += wv.w*av.y; acc[3][2] += wv.w*av.z; acc[3][3] += wv.w*av.w;
        }
        __syncthreads();
        #pragma unroll
        for (int i = 0; i < 4; ++i)
            #pragma unroll
            for (int j = 0; j < 4; ++j) t[oo0+i][t0+j] = acc[i][j];
        __syncthreads();
        for (int idx = tid; idx < 64*64; idx += 256) {
            int tok = idx >> 6, o = idx & 63;
            int dd = o0 + o;
            float v = t[o][tok];
            int n = n0 + tok;
            if (dd < DI) g_xm[(size_t)n*DI + dd]      = v;
            else         g_z [(size_t)n*DI + dd - DI] = v;
        }
    }
}

// ======== K2: conv1d+SiLU + x_proj + dt + local chunk scan ===============
// dyn smem: xmS[67][132] | xcS[64][129] | dbc[64][40]
#define XM_PITCH 132
#define XC_PITCH 129
__global__ __launch_bounds__(256) void k_fuse2(
        const float* __restrict__ cw, const float* __restrict__ cb,
        const float* __restrict__ xpw,
        const float* __restrict__ dtpw, const float* __restrict__ dtpb) {
    extern __shared__ __align__(16) float sm[];
    float* xmS = sm;                      // 67*132 = 8844 (later reused: dt rows 0..63, then E/P staging)
    float* xcS = sm + 8844;               // 64*129 = 8256
    float* dbc = sm + 8844 + 8256;        // 64*40  = 2560
    int blk = blockIdx.x;                 // b*64 + g
    int g = blk & 63;
    int tid = threadIdx.x;
    int n0 = blk * TCH;

    // phase A: load xm tile with 3-token halo, compute xc = silu(conv1d)
    for (int idx = tid; idx < 67*DI; idx += 256) {
        int i = idx >> 7, d = idx & 127;
        float v = 0.f;
        if (g > 0 || i >= 3) v = g_xm[(size_t)(n0 - 3 + i)*DI + d];
        xmS[i*XM_PITCH + d] = v;
    }
    __syncthreads();
    for (int idx = tid; idx < 64*DI; idx += 256) {
        int tok = idx >> 7, d = idx & 127;
        float acc = __ldg(&cb[d]);
        #pragma unroll
        for (int k = 0; k < 4; ++k)
            acc += __ldg(&cw[d*4 + k]) * xmS[(tok + k)*XM_PITCH + d];
        float v = siluf(acc);
        xcS[tok*XC_PITCH + d] = v;
        g_xc[(size_t)(n0+tok)*DI + d] = v;
    }
    __syncthreads();

    // phase B: dbc = xc @ xpw^T   (36 outs x 64 toks x 128 K)
    int eg = tid >> 4, tg = tid & 15;
    if (eg < 9) {
        int e0 = eg*4, t0 = tg*4;
        float acc[4][4] = {};
        #pragma unroll 4
        for (int ci = 0; ci < DI; ++ci) {
            float w0_ = __ldg(&xpw[(e0+0)*DI + ci]);
            float w1_ = __ldg(&xpw[(e0+1)*DI + ci]);
            float w2_ = __ldg(&xpw[(e0+2)*DI + ci]);
            float w3_ = __ldg(&xpw[(e0+3)*DI + ci]);
            float a0_ = xcS[(t0+0)*XC_PITCH + ci];
            float a1_ = xcS[(t0+1)*XC_PITCH + ci];
            float a2_ = xcS[(t0+2)*XC_PITCH + ci];
            float a3_ = xcS[(t0+3)*XC_PITCH + ci];
            acc[0][0] += w0_*a0_; acc[0][1] += w0_*a1_; acc[0][2] += w0_*a2_; acc[0][3] += w0_*a3_;
            acc[1][0] += w1_*a0_; acc[1][1] += w1_*a1_; acc[1][2] += w1_*a2_; acc[1][3] += w1_*a3_;
            acc[2][0] += w2_*a0_; acc[2][1] += w2_*a1_; acc[2][2] += w2_*a2_; acc[2][3] += w2_*a3_;
            acc[3][0] += w3_*a0_; acc[3][1] += w3_*a1_; acc[3][2] += w3_*a2_; acc[3][3] += w3_*a3_;
        }
        #pragma unroll
        for (int i = 0; i < 4; ++i)
            #pragma unroll
            for (int j = 0; j < 4; ++j) dbc[(t0+j)*40 + e0+i] = acc[i][j];
    }
    __syncthreads();

    // phase C: dt = softplus(dbc[:,0:4] @ dtpw^T + b) -> overwrite xmS rows 0..63
    for (int idx = tid; idx < 64*DI; idx += 256) {
        int tok = idx >> 7, d = idx & 127;
        float raw = __ldg(&dtpb[d]);
        #pragma unroll
        for (int rr = 0; rr < DTR; ++rr) raw += dbc[tok*40 + rr] * __ldg(&dtpw[d*DTR + rr]);
        float dt = (raw > 20.f) ? raw : log1pf(__expf(raw));
        xmS[tok*XM_PITCH + d] = dt;
    }
    // export C for K4
    for (int idx = tid; idx < 64*DS; idx += 256) {
        int tok = idx >> 4, s = idx & 15;
        g_Cm[(size_t)(n0+tok)*DS + s] = dbc[tok*40 + 20 + s];
    }
    __syncthreads();

    // phase D: local scan (zero-init), threads 0..127 = d
    float hreg[DS];
    float cd = 0.f;
    int d = tid;
    if (d < DI) {
        float a0 = g_A[d*DS];
        bool chain = (g_chain[d] != 0);
        float As[DS];
        #pragma unroll
        for (int s = 0; s < DS; ++s) As[s] = g_A[d*DS + s];
        #pragma unroll
        for (int s = 0; s < DS; ++s) hreg[s] = 0.f;

        if (chain) {
            for (int st = 0; st < TCH; ++st) {
                float dtv = xmS[st*XM_PITCH + d];
                float xcv = xcS[st*XC_PITCH + d];
                float dxv = dtv * xcv;
                cd += dtv;
                float e1 = __expf(dtv * a0);
                float e2 = e1*e1, e3 = e2*e1, e4 = e2*e2;
                float pe0 = e1, pe1 = e2, pe2 = e3, pe3 = e4;
                float base = 1.f;
                float y = 0.f;
                #pragma unroll
                for (int gq = 0; gq < 4; ++gq) {
                    int s0 = gq*4;
                    float p0 = base*pe0, p1 = base*pe1, p2 = base*pe2, p3 = base*pe3;
                    hreg[s0+0] = p0*hreg[s0+0] + dxv*dbc[st*40 + 4 + s0+0];
                    hreg[s0+1] = p1*hreg[s0+1] + dxv*dbc[st*40 + 4 + s0+1];
                    hreg[s0+2] = p2*hreg[s0+2] + dxv*dbc[st*40 + 4 + s0+2];
                    hreg[s0+3] = p3*hreg[s0+3] + dxv*dbc[st*40 + 4 + s0+3];
                    y += hreg[s0+0]*dbc[st*40 + 20 + s0+0];
                    y += hreg[s0+1]*dbc[st*40 + 20 + s0+1];
                    y += hreg[s0+2]*dbc[st*40 + 20 + s0+2];
                    y += hreg[s0+3]*dbc[st*40 + 20 + s0+3];
                    base *= e4;
                }
                size_t gi = (size_t)(n0+st)*DI + d;
                g_yl[gi] = y; g_cd[gi] = cd;
            }
        } else {
            for (int st = 0; st < TCH; ++st) {
                float dtv = xmS[st*XM_PITCH + d];
                float xcv = xcS[st*XC_PITCH + d];
                float dxv = dtv * xcv;
                cd += dtv;
                float y = 0.f;
                #pragma unroll
                for (int s = 0; s < DS; ++s) {
                    float dA = __expf(dtv * As[s]);
                    hreg[s] = dA*hreg[s] + dxv*dbc[st*40 + 4 + s];
                    y += hreg[s]*dbc[st*40 + 20 + s];
                }
                size_t gi = (size_t)(n0+st)*DI + d;
                g_yl[gi] = y; g_cd[gi] = cd;
            }
        }
    }
    __syncthreads();   // all dt reads done before staging overwrites xmS
    if (d < DI) {
        float* stgE = xmS;          // 2048 floats
        float* stgP = xmS + 2048;   // 2048 floats
        float a0 = g_A[d*DS];
        bool chain = (g_chain[d] != 0);
        #pragma unroll
        for (int s = 0; s < DS; ++s) stgE[d*DS + s] = hreg[s];
        if (chain) {
            float q = __expf(a0 * cd);
            float q2 = q*q, q3 = q2*q, q4 = q2*q2;
            float base = 1.f;
            #pragma unroll
            for (int gq = 0; gq < 4; ++gq) {
                stgP[d*DS + gq*4+0] = base*q;
                stgP[d*DS + gq*4+1] = base*q2;
                stgP[d*DS + gq*4+2] = base*q3;
                stgP[d*DS + gq*4+3] = base*q4;
                base *= q4;
            }
        } else {
            #pragma unroll
            for (int s = 0; s < DS; ++s) stgP[d*DS + s] = __expf(g_A[d*DS+s]*cd);
        }
    }
    __syncthreads();
    for (int idx = tid; idx < DI*DS; idx += 256) {
        g_E[(size_t)blk*DI*DS + idx] = xmS[idx];
        g_P[(size_t)blk*DI*DS + idx] = xmS[2048 + idx];
    }
}

// ---------------- K3: sequential chunk-state combine (pipelined) ---------
// 8192 lanes (b,d,s). Loads for all 64 chunks are independent of the scan
// value h, so double-buffer 8 (P,E) pairs per group -> MLP~16 instead of 1.
__global__ __launch_bounds__(128) void k_comb() {
    int i = blockIdx.x * 128 + threadIdx.x;    // 8192 = BZ*DI*DS
    int b = i >> 11, r = i & 2047;
    size_t base = (size_t)b*GCH*(DI*DS) + r;

    float Pb[8], Eb[8];
    #pragma unroll
    for (int j = 0; j < 8; ++j) {
        Pb[j] = g_P[base + (size_t)j*(DI*DS)];
        Eb[j] = g_E[base + (size_t)j*(DI*DS)];
    }
    float h = 0.f;
    #pragma unroll
    for (int grp = 0; grp < 8; ++grp) {
        float Pn[8], En[8];
        if (grp < 7) {
            #pragma unroll
            for (int j = 0; j < 8; ++j) {
                size_t o = base + (size_t)((grp+1)*8 + j)*(DI*DS);
                Pn[j] = g_P[o];
                En[j] = g_E[o];
            }
        }
        #pragma unroll
        for (int j = 0; j < 8; ++j) {
            g_H[base + (size_t)(grp*8 + j)*(DI*DS)] = h;
            h = fmaf(Pb[j], h, Eb[j]);
        }
        if (grp < 7) {
            #pragma unroll
            for (int j = 0; j < 8; ++j) { Pb[j] = Pn[j]; Eb[j] = En[j]; }
        }
    }
}

// ======== K4: correction + gating + out_proj + residual + NCHW ===========
// dyn smem: ysT[128][68] | wT[128][68] | seqT[64][68] | Hs[128][17] | Cs[64][16] | a0s|dps|chs
__global__ __launch_bounds__(256) void k_fuse4(const float* __restrict__ Dp,
                                               const float* __restrict__ Wout,
                                               float* __restrict__ out) {
    extern __shared__ __align__(16) float sm[];
    float* ysT  = sm;                    // [128][68]
    float* wT   = sm + 8704;             // [128][68]
    float* seqT = sm + 17408;            // [64][68]
    float* Hs   = sm + 21760;            // [128][17]
    float* Cs   = sm + 23936;            // [64][16]
    float* a0s  = sm + 24960;            // [128]
    float* dps  = sm + 25088;            // [128]
    float* chs  = sm + 25216;            // [128]
    int blk = blockIdx.x;                // b*64 + g
    int b = blk >> 6, g = blk & 63;
    int n0 = blk * 64;
    int l0 = g * 64;
    int tid = threadIdx.x;

    for (int idx = tid; idx < DI*DS; idx += 256)
        Hs[(idx >> 4)*17 + (idx & 15)] = g_H[(size_t)blk*DI*DS + idx];
    for (int idx = tid; idx < 64*DS; idx += 256)
        Cs[idx] = g_Cm[(size_t)n0*DS + idx];
    if (tid < DI) {
        a0s[tid] = g_A[tid*DS];
        dps[tid] = Dp[tid];
        chs[tid] = (float)g_chain[tid];
    }
    for (int idx = tid; idx < DI*CH; idx += 256) {
        int d = idx & 127, c = idx >> 7;
        wT[d*68 + c] = Wout[c*DI + d];
    }
    for (int idx = tid; idx < 64*CH; idx += 256) {
        int tok = idx >> 6, c = idx & 63;
        seqT[c*68 + tok] = g_seq[(size_t)(n0+tok)*CH + c];
    }
    __syncthreads();

    // correction + gating -> ysT[d][tok]
    for (int idx = tid; idx < 64*DI; idx += 256) {
        int tok = idx >> 7, d = idx & 127;
        size_t gi = (size_t)(n0+tok)*DI + d;
        float cdv = g_cd[gi];
        float y   = g_yl[gi];
        float xcv = g_xc[gi];
        float zv  = g_z[gi];
        if (chs[d] != 0.f) {
            float q = __expf(a0s[d] * cdv);
            float poly = Cs[tok*16 + 15] * Hs[d*17 + 15];
            #pragma unroll
            for (int s = 14; s >= 0; --s)
                poly = fmaf(q, poly, Cs[tok*16 + s] * Hs[d*17 + s]);
            y += q * poly;
        } else {
            #pragma unroll
            for (int s = 0; s < DS; ++s)
                y += Cs[tok*16 + s] * __expf(g_A[d*DS + s]*cdv) * Hs[d*17 + s];
        }
        ysT[d*68 + tok] = (y + xcv*dps[d]) * siluf(zv);
    }
    __syncthreads();

    // out_proj GEMM [64c x 64tok x 128K] + residual
    int cg = tid >> 4, tg = tid & 15;
    int c0 = cg*4, t0 = tg*4;
    float acc[4][4] = {};
    #pragma unroll 4
    for (int d = 0; d < DI; ++d) {
        float4 av = *(const float4*)&ysT[d*68 + t0];
        float4 wv = *(const float4*)&wT[d*68 + c0];
        acc[0][0] += wv.x*av.x; acc[0][1] += wv.x*av.y; acc[0][2] += wv.x*av.z; acc[0][3] += wv.x*av.w;
        acc[1][0] += wv.y*av.x; acc[1][1] += wv.y*av.y; acc[1][2] += wv.y*av.z; acc[1][3] += wv.y*av.w;
        acc[2][0] += wv.z*av.x; acc[2][1] += wv.z*av.y; acc[2][2] += wv.z*av.z; acc[2][3] += wv.z*av.w;
        acc[3][0] += wv.w*av.x; acc[3][1] += wv.w*av.y; acc[3][2] += wv.w*av.z; acc[3][3] += wv.w*av.w;
    }
    #pragma unroll
    for (int i = 0; i < 4; ++i)
        #pragma unroll
        for (int j = 0; j < 4; ++j) acc[i][j] += seqT[(c0+i)*68 + t0+j];
    __syncthreads();
    #pragma unroll
    for (int i = 0; i < 4; ++i)
        #pragma unroll
        for (int j = 0; j < 4; ++j) wT[(c0+i)*68 + t0+j] = acc[i][j];
    __syncthreads();
    for (int idx = tid; idx < CH*64; idx += 256) {
        int c = idx >> 6, tok = idx & 63;
        out[((size_t)(b*CH + c))*LSEQ + l0 + tok] = wT[c*68 + tok];
    }
}

// ---------------- launch --------------------------------------------------
extern "C" void kernel_launch(void* const* d_in, const int* in_sizes, int n_in,
                              void* d_out, int out_size) {
    const float* x       = (const float*)d_in[0];
    const float* dwh_w   = (const float*)d_in[1];
    const float* dwh_b   = (const float*)d_in[2];
    const float* dww_w   = (const float*)d_in[3];
    const float* dww_b   = (const float*)d_in[4];
    const float* conv_w  = (const float*)d_in[5];
    const float* conv_b  = (const float*)d_in[6];
    const float* bn_g    = (const float*)d_in[7];
    const float* bn_b    = (const float*)d_in[8];
    const float* bn_m    = (const float*)d_in[9];
    const float* bn_v    = (const float*)d_in[10];
    const float* ln_g    = (const float*)d_in[11];
    const float* ln_b    = (const float*)d_in[12];
    const float* in_proj = (const float*)d_in[13];
    const float* convd_w = (const float*)d_in[14];
    const float* convd_b = (const float*)d_in[15];
    const float* x_proj  = (const float*)d_in[16];
    const float* dt_w    = (const float*)d_in[17];
    const float* dt_b    = (const float*)d_in[18];
    const float* A_log   = (const float*)d_in[19];
    const float* Dp      = (const float*)d_in[20];
    const float* out_w   = (const float*)d_in[21];
    float* out = (float*)d_out;

    cudaFuncSetAttribute(k_fuse2, cudaFuncAttributeMaxDynamicSharedMemorySize, 78640);
    cudaFuncSetAttribute(k_fuse4, cudaFuncAttributeMaxDynamicSharedMemorySize, 101376);

    k_initA<<<1, DI>>>(A_log);
    k_fuse1<<<BZ*HH, 256>>>(x, dwh_w, dwh_b, dww_w, dww_b, conv_w, conv_b,
                            bn_g, bn_b, bn_m, bn_v, ln_g, ln_b, in_proj);
    k_fuse2<<<BZ*GCH, 256, 78640>>>(convd_w, convd_b, x_proj, dt_w, dt_b);
    k_comb<<<64, 128>>>();
    k_fuse4<<<BZ*GCH, 256, 101376>>>(Dp, out_w, out);
}

// round 9
// speedup vs baseline: 1.7621x; 1.0040x over previous
#include <cuda_runtime.h>
#include <math.h>

#define BZ   4
#define CH   64
#define HH   64
#define WW   64
#define LSEQ (HH*WW)      // 4096
#define NT   (BZ*LSEQ)    // 16384
#define DI   128
#define DS   16
#define DTR  4
#define GCH  64           // chunks per batch
#define TCH  (LSEQ/GCH)   // 64 steps per chunk

// ---------------- scratch (device globals; no allocation) ----------------
__device__ float g_seq[NT*CH];
__device__ float g_xm [NT*DI];
__device__ float g_z  [NT*DI];
__device__ float g_xc [NT*DI];
__device__ float g_Cm [NT*DS];
__device__ float g_yl [NT*DI];
__device__ float g_cd [NT*DI];
__device__ float g_E  [BZ*GCH*DI*DS];
__device__ float g_P  [BZ*GCH*DI*DS];
__device__ float g_H  [BZ*GCH*DI*DS];
__device__ float g_A  [DI*DS];
__device__ int   g_chain[DI];

__device__ __forceinline__ float siluf(float v) { return v / (1.f + __expf(-v)); }

// ======== K1: axial DW + 1x1 conv + BN + ReLU + LN + in_proj GEMM ========
// (block 0 also initializes g_A/g_chain; consumers run in later kernels)
// dyn smem: t[64][68] | r[64][68] | wB (8576 floats: weights [64][132] or staging [128][67])
__global__ __launch_bounds__(256) void k_fuse1(
        const float* __restrict__ x,
        const float* __restrict__ dwhw, const float* __restrict__ dwhb,
        const float* __restrict__ dwww, const float* __restrict__ dwwb,
        const float* __restrict__ convw, const float* __restrict__ convb,
        const float* __restrict__ bng, const float* __restrict__ bnb,
        const float* __restrict__ bnm, const float* __restrict__ bnv,
        const float* __restrict__ lng, const float* __restrict__ lnb,
        const float* __restrict__ Win, const float* __restrict__ A_log) {
    extern __shared__ __align__(16) float sm1[];
    float* t  = sm1;               // [64][68]
    float* r  = sm1 + 64*68;       // [64][68]
    float* wB = sm1 + 2*64*68;     // 8576 floats
    __shared__ float mu[WW], rs[WW];
    __shared__ float sc[CH], sh[CH];
    int blk = blockIdx.x;
    int b = blk >> 6, h = blk & 63;
    int tid = threadIdx.x;

    // fold former k_initA: A = -exp(A_log), detect integer-power structure
    if (blk == 0 && tid < DI) {
        int d = tid;
        float a0 = -expf(A_log[d*DS + 0]);
        int ok = 1;
        for (int s = 0; s < DS; ++s) {
            float a = -expf(A_log[d*DS + s]);
            g_A[d*DS + s] = a;
            if (fabsf(a - (float)(s+1)*a0) > 1e-3f*fabsf(a) + 1e-6f) ok = 0;
        }
        g_chain[d] = ok;
    }

    if (tid < CH) {
        float s = bng[tid] * rsqrtf(bnv[tid] + 1e-5f);
        sc[tid] = s;
        sh[tid] = (convb[tid] - bnm[tid]) * s + bnb[tid];
    }
    const float* xb = x + (size_t)b*CH*LSEQ;
    for (int idx = tid; idx < CH*WW; idx += 256) {
        int c = idx >> 6, w = idx & 63;
        const float* xr = xb + c*LSEQ + h*WW;
        float xv = xr[w];
        float up = (h > 0)    ? xr[w - WW] : 0.f;
        float dn = (h < HH-1) ? xr[w + WW] : 0.f;
        float lf = (w > 0)    ? xr[w - 1]  : 0.f;
        float rt = (w < WW-1) ? xr[w + 1]  : 0.f;
        float v = xv
            + dwhw[c*3+0]*up + dwhw[c*3+1]*xv + dwhw[c*3+2]*dn + dwhb[c]
            + dwww[c*3+0]*lf + dwww[c*3+1]*xv + dwww[c*3+2]*rt + dwwb[c];
        t[c*68 + w] = v;
    }
    __syncthreads();

    // 1x1 conv (64x64x64) -> BN -> ReLU into r
    int cg = tid >> 4, tg = tid & 15;
    int co0 = cg * 4, w0 = tg * 4;
    {
        float acc[4][4] = {};
        #pragma unroll 4
        for (int ci = 0; ci < CH; ++ci) {
            float4 av = *(const float4*)&t[ci*68 + w0];
            float wv0 = __ldg(&convw[(co0+0)*CH + ci]);
            float wv1 = __ldg(&convw[(co0+1)*CH + ci]);
            float wv2 = __ldg(&convw[(co0+2)*CH + ci]);
            float wv3 = __ldg(&convw[(co0+3)*CH + ci]);
            acc[0][0] += wv0*av.x; acc[0][1] += wv0*av.y; acc[0][2] += wv0*av.z; acc[0][3] += wv0*av.w;
            acc[1][0] += wv1*av.x; acc[1][1] += wv1*av.y; acc[1][2] += wv1*av.z; acc[1][3] += wv1*av.w;
            acc[2][0] += wv2*av.x; acc[2][1] += wv2*av.y; acc[2][2] += wv2*av.z; acc[2][3] += wv2*av.w;
            acc[3][0] += wv3*av.x; acc[3][1] += wv3*av.y; acc[3][2] += wv3*av.z; acc[3][3] += wv3*av.w;
        }
        #pragma unroll
        for (int i = 0; i < 4; ++i)
            #pragma unroll
            for (int j = 0; j < 4; ++j) {
                float v = acc[i][j]*sc[co0+i] + sh[co0+i];
                r[(co0+i)*68 + w0+j] = fmaxf(v, 0.f);
            }
    }
    __syncthreads();

    if (tid < WW) {
        float m = 0.f;
        for (int c = 0; c < CH; ++c) m += r[c*68 + tid];
        m *= (1.f/CH);
        float v = 0.f;
        for (int c = 0; c < CH; ++c) { float dd = r[c*68 + tid] - m; v += dd*dd; }
        v *= (1.f/CH);
        mu[tid] = m; rs[tid] = rsqrtf(v + 1e-5f);
    }
    __syncthreads();

    int n0 = b*LSEQ + h*WW;
    // store seq; normalize r in place -> hn[c][tok]
    for (int idx = tid; idx < CH*WW; idx += 256) {
        int w = idx >> 6, c = idx & 63;
        float rv = r[c*68 + w];
        g_seq[(size_t)(n0+w)*CH + c] = rv;
        r[c*68 + w] = (rv - mu[w]) * rs[w] * lng[c] + lnb[c];
    }

    // in_proj GEMM: hn[64tok x 64c] x Win[256 x 64]^T, 2 chunks of 128 outs,
    // 8x4 microtile (32 FMA per 3 LDS.128)
    int oo0 = cg*4, t0 = tg*4;
    for (int chunk = 0; chunk < 2; ++chunk) {
        int o0 = chunk * 128;
        __syncthreads();
        for (int idx = tid; idx < 128*CH; idx += 256) {
            int oo = idx >> 6, c = idx & 63;
            wB[c*132 + oo] = Win[(o0+oo)*CH + c];
        }
        __syncthreads();
        float acc[8][4] = {};
        #pragma unroll 2
        for (int ci = 0; ci < CH; ++ci) {
            float4 av = *(const float4*)&r[ci*68 + t0];
            float4 u  = *(const float4*)&wB[ci*132 + oo0];
            float4 v  = *(const float4*)&wB[ci*132 + oo0 + 64];
            acc[0][0] += u.x*av.x; acc[0][1] += u.x*av.y; acc[0][2] += u.x*av.z; acc[0][3] += u.x*av.w;
            acc[1][0] += u.y*av.x; acc[1][1] += u.y*av.y; acc[1][2] += u.y*av.z; acc[1][3] += u.y*av.w;
            acc[2][0] += u.z*av.x; acc[2][1] += u.z*av.y; acc[2][2] += u.z*av.z; acc[2][3] += u.z*av.w;
            acc[3][0] += u.w*av.x; acc[3][1] += u.w*av.y; acc[3][2] += u.w*av.z; acc[3][3] += u.w*av.w;
            acc[4][0] += v.x*av.x; acc[4][1] += v.x*av.y; acc[4][2] += v.x*av.z; acc[4][3] += v.x*av.w;
            acc[5][0] += v.y*av.x; acc[5][1] += v.y*av.y; acc[5][2] += v.y*av.z; acc[5][3] += v.y*av.w;
            acc[6][0] += v.z*av.x; acc[6][1] += v.z*av.y; acc[6][2] += v.z*av.z; acc[6][3] += v.z*av.w;
            acc[7][0] += v.w*av.x; acc[7][1] += v.w*av.y; acc[7][2] += v.w*av.z; acc[7][3] += v.w*av.w;
        }
        __syncthreads();
        // stage into wB viewed as [128][67]
        #pragma unroll
        for (int i = 0; i < 4; ++i)
            #pragma unroll
            for (int j = 0; j < 4; ++j) {
                wB[(oo0+i)*67 + t0+j]    = acc[i][j];
                wB[(oo0+64+i)*67 + t0+j] = acc[4+i][j];
            }
        __syncthreads();
        for (int idx = tid; idx < 128*64; idx += 256) {
            int tok = idx >> 7, oo = idx & 127;
            float vv = wB[oo*67 + tok];
            int n = n0 + tok;
            if (chunk == 0) g_xm[(size_t)n*DI + oo] = vv;
            else            g_z [(size_t)n*DI + oo] = vv;
        }
    }
}

// ======== K2: conv1d+SiLU + x_proj + dt + local chunk scan ===============
// dyn smem: xmS[67][132] | xcS[64][129] | dbc[64][40]
#define XM_PITCH 132
#define XC_PITCH 129
__global__ __launch_bounds__(256) void k_fuse2(
        const float* __restrict__ cw, const float* __restrict__ cb,
        const float* __restrict__ xpw,
        const float* __restrict__ dtpw, const float* __restrict__ dtpb) {
    extern __shared__ __align__(16) float sm[];
    float* xmS = sm;                      // 67*132 = 8844 (later: dt rows 0..63, then E/P staging)
    float* xcS = sm + 8844;               // 64*129 = 8256
    float* dbc = sm + 8844 + 8256;        // 64*40  = 2560
    int blk = blockIdx.x;                 // b*64 + g
    int g = blk & 63;
    int tid = threadIdx.x;
    int n0 = blk * TCH;

    // phase A: load xm tile with 3-token halo, compute xc = silu(conv1d)
    for (int idx = tid; idx < 67*DI; idx += 256) {
        int i = idx >> 7, d = idx & 127;
        float v = 0.f;
        if (g > 0 || i >= 3) v = g_xm[(size_t)(n0 - 3 + i)*DI + d];
        xmS[i*XM_PITCH + d] = v;
    }
    __syncthreads();
    for (int idx = tid; idx < 64*DI; idx += 256) {
        int tok = idx >> 7, d = idx & 127;
        float acc = __ldg(&cb[d]);
        #pragma unroll
        for (int k = 0; k < 4; ++k)
            acc += __ldg(&cw[d*4 + k]) * xmS[(tok + k)*XM_PITCH + d];
        float v = siluf(acc);
        xcS[tok*XC_PITCH + d] = v;
        g_xc[(size_t)(n0+tok)*DI + d] = v;
    }
    __syncthreads();

    // phase B: dbc = xc @ xpw^T   (36 outs x 64 toks x 128 K)
    int eg = tid >> 4, tg = tid & 15;
    if (eg < 9) {
        int e0 = eg*4, t0 = tg*4;
        float acc[4][4] = {};
        #pragma unroll 4
        for (int ci = 0; ci < DI; ++ci) {
            float w0_ = __ldg(&xpw[(e0+0)*DI + ci]);
            float w1_ = __ldg(&xpw[(e0+1)*DI + ci]);
            float w2_ = __ldg(&xpw[(e0+2)*DI + ci]);
            float w3_ = __ldg(&xpw[(e0+3)*DI + ci]);
            float a0_ = xcS[(t0+0)*XC_PITCH + ci];
            float a1_ = xcS[(t0+1)*XC_PITCH + ci];
            float a2_ = xcS[(t0+2)*XC_PITCH + ci];
            float a3_ = xcS[(t0+3)*XC_PITCH + ci];
            acc[0][0] += w0_*a0_; acc[0][1] += w0_*a1_; acc[0][2] += w0_*a2_; acc[0][3] += w0_*a3_;
            acc[1][0] += w1_*a0_; acc[1][1] += w1_*a1_; acc[1][2] += w1_*a2_; acc[1][3] += w1_*a3_;
            acc[2][0] += w2_*a0_; acc[2][1] += w2_*a1_; acc[2][2] += w2_*a2_; acc[2][3] += w2_*a3_;
            acc[3][0] += w3_*a0_; acc[3][1] += w3_*a1_; acc[3][2] += w3_*a2_; acc[3][3] += w3_*a3_;
        }
        #pragma unroll
        for (int i = 0; i < 4; ++i)
            #pragma unroll
            for (int j = 0; j < 4; ++j) dbc[(t0+j)*40 + e0+i] = acc[i][j];
    }
    __syncthreads();

    // phase C: dt = softplus(dbc[:,0:4] @ dtpw^T + b) -> overwrite xmS rows 0..63
    for (int idx = tid; idx < 64*DI; idx += 256) {
        int tok = idx >> 7, d = idx & 127;
        float raw = __ldg(&dtpb[d]);
        #pragma unroll
        for (int rr = 0; rr < DTR; ++rr) raw += dbc[tok*40 + rr] * __ldg(&dtpw[d*DTR + rr]);
        float dt = (raw > 20.f) ? raw : log1pf(__expf(raw));
        xmS[tok*XM_PITCH + d] = dt;
    }
    // export C for K4
    for (int idx = tid; idx < 64*DS; idx += 256) {
        int tok = idx >> 4, s = idx & 15;
        g_Cm[(size_t)(n0+tok)*DS + s] = dbc[tok*40 + 20 + s];
    }
    __syncthreads();

    // phase D: local scan (zero-init), paired lanes: thread = (d, half),
    // lanes 2d / 2d+1 in same warp handle states [half*8, half*8+8)
    int d = tid >> 1, half = tid & 1;
    float hreg[8];
    float cd = 0.f;
    {
        float a0 = g_A[d*DS];
        bool chain = (g_chain[d] != 0);
        float As[8];
        #pragma unroll
        for (int j = 0; j < 8; ++j) As[j] = g_A[d*DS + half*8 + j];
        #pragma unroll
        for (int j = 0; j < 8; ++j) hreg[j] = 0.f;
        const float* Bp = dbc + 4 + half*8;
        const float* Cp = dbc + 20 + half*8;

        if (chain) {
            for (int st = 0; st < TCH; ++st) {
                float dtv = xmS[st*XM_PITCH + d];
                float xcv = xcS[st*XC_PITCH + d];
                float dxv = dtv * xcv;
                cd += dtv;
                float e1 = __expf(dtv * a0);
                float e2 = e1*e1, e3 = e2*e1, e4 = e2*e2;
                float e5 = e4*e1, e6 = e4*e2, e7 = e4*e3, e8 = e4*e4;
                float base = half ? e8 : 1.f;
                float p0 = base*e1, p1 = base*e2, p2 = base*e3, p3 = base*e4;
                float p4 = base*e5, p5 = base*e6, p6 = base*e7, p7 = base*e8;
                const float* Bs = Bp + st*40;
                const float* Cs_ = Cp + st*40;
                float y;
                hreg[0] = p0*hreg[0] + dxv*Bs[0];  y  = hreg[0]*Cs_[0];
                hreg[1] = p1*hreg[1] + dxv*Bs[1];  y += hreg[1]*Cs_[1];
                hreg[2] = p2*hreg[2] + dxv*Bs[2];  y += hreg[2]*Cs_[2];
                hreg[3] = p3*hreg[3] + dxv*Bs[3];  y += hreg[3]*Cs_[3];
                hreg[4] = p4*hreg[4] + dxv*Bs[4];  y += hreg[4]*Cs_[4];
                hreg[5] = p5*hreg[5] + dxv*Bs[5];  y += hreg[5]*Cs_[5];
                hreg[6] = p6*hreg[6] + dxv*Bs[6];  y += hreg[6]*Cs_[6];
                hreg[7] = p7*hreg[7] + dxv*Bs[7];  y += hreg[7]*Cs_[7];
                y += __shfl_xor_sync(0xffffffffu, y, 1);
                if (half == 0) {
                    size_t gi = (size_t)(n0+st)*DI + d;
                    g_yl[gi] = y; g_cd[gi] = cd;
                }
            }
        } else {
            for (int st = 0; st < TCH; ++st) {
                float dtv = xmS[st*XM_PITCH + d];
                float xcv = xcS[st*XC_PITCH + d];
                float dxv = dtv * xcv;
                cd += dtv;
                const float* Bs = Bp + st*40;
                const float* Cs_ = Cp + st*40;
                float y = 0.f;
                #pragma unroll
                for (int j = 0; j < 8; ++j) {
                    float dA = __expf(dtv * As[j]);
                    hreg[j] = dA*hreg[j] + dxv*Bs[j];
                    y += hreg[j]*Cs_[j];
                }
                y += __shfl_xor_sync(0xffffffffu, y, 1);
                if (half == 0) {
                    size_t gi = (size_t)(n0+st)*DI + d;
                    g_yl[gi] = y; g_cd[gi] = cd;
                }
            }
        }
    }
    __syncthreads();   // all dt/xc reads done before staging overwrites xmS
    {
        float* stgE = xmS;          // 2048 floats
        float* stgP = xmS + 2048;   // 2048 floats
        float a0 = g_A[d*DS];
        bool chain = (g_chain[d] != 0);
        int sb = d*DS + half*8;
        #pragma unroll
        for (int j = 0; j < 8; ++j) stgE[sb + j] = hreg[j];
        if (chain) {
            float q = __expf(a0 * cd);
            float q2 = q*q, q3 = q2*q, q4 = q2*q2;
            float q5 = q4*q, q6 = q4*q2, q7 = q4*q3, q8 = q4*q4;
            float base = half ? q8 : 1.f;
            stgP[sb+0] = base*q;  stgP[sb+1] = base*q2;
            stgP[sb+2] = base*q3; stgP[sb+3] = base*q4;
            stgP[sb+4] = base*q5; stgP[sb+5] = base*q6;
            stgP[sb+6] = base*q7; stgP[sb+7] = base*q8;
        } else {
            #pragma unroll
            for (int j = 0; j < 8; ++j)
                stgP[sb + j] = __expf(g_A[d*DS + half*8 + j]*cd);
        }
    }
    __syncthreads();
    for (int idx = tid; idx < DI*DS; idx += 256) {
        g_E[(size_t)blk*DI*DS + idx] = xmS[idx];
        g_P[(size_t)blk*DI*DS + idx] = xmS[2048 + idx];
    }
}

// ---------------- K3: sequential chunk-state combine (pipelined) ---------
__global__ __launch_bounds__(128) void k_comb() {
    int i = blockIdx.x * 128 + threadIdx.x;    // 8192 = BZ*DI*DS
    int b = i >> 11, r = i & 2047;
    size_t base = (size_t)b*GCH*(DI*DS) + r;

    float Pb[8], Eb[8];
    #pragma unroll
    for (int j = 0; j < 8; ++j) {
        Pb[j] = g_P[base + (size_t)j*(DI*DS)];
        Eb[j] = g_E[base + (size_t)j*(DI*DS)];
    }
    float h = 0.f;
    #pragma unroll
    for (int grp = 0; grp < 8; ++grp) {
        float Pn[8], En[8];
        if (grp < 7) {
            #pragma unroll
            for (int j = 0; j < 8; ++j) {
                size_t o = base + (size_t)((grp+1)*8 + j)*(DI*DS);
                Pn[j] = g_P[o];
                En[j] = g_E[o];
            }
        }
        #pragma unroll
        for (int j = 0; j < 8; ++j) {
            g_H[base + (size_t)(grp*8 + j)*(DI*DS)] = h;
            h = fmaf(Pb[j], h, Eb[j]);
        }
        if (grp < 7) {
            #pragma unroll
            for (int j = 0; j < 8; ++j) { Pb[j] = Pn[j]; Eb[j] = En[j]; }
        }
    }
}

// ======== K4: correction + gating + out_proj + residual + NCHW ===========
// dyn smem: ysT[128][68] | wT[128][68] | seqT[64][68] | Hs[128][17] | Cs[64][16] | a0s|dps|chs
__global__ __launch_bounds__(256) void k_fuse4(const float* __restrict__ Dp,
                                               const float* __restrict__ Wout,
                                               float* __restrict__ out) {
    extern __shared__ __align__(16) float sm[];
    float* ysT  = sm;                    // [128][68]
    float* wT   = sm + 8704;             // [128][68]
    float* seqT = sm + 17408;            // [64][68]
    float* Hs   = sm + 21760;            // [128][17]
    float* Cs   = sm + 23936;            // [64][16]
    float* a0s  = sm + 24960;            // [128]
    float* dps  = sm + 25088;            // [128]
    float* chs  = sm + 25216;            // [128]
    int blk = blockIdx.x;                // b*64 + g
    int b = blk >> 6, g = blk & 63;
    int n0 = blk * 64;
    int l0 = g * 64;
    int tid = threadIdx.x;

    for (int idx = tid; idx < DI*DS; idx += 256)
        Hs[(idx >> 4)*17 + (idx & 15)] = g_H[(size_t)blk*DI*DS + idx];
    for (int idx = tid; idx < 64*DS; idx += 256)
        Cs[idx] = g_Cm[(size_t)n0*DS + idx];
    if (tid < DI) {
        a0s[tid] = g_A[tid*DS];
        dps[tid] = Dp[tid];
        chs[tid] = (float)g_chain[tid];
    }
    for (int idx = tid; idx < DI*CH; idx += 256) {
        int d = idx & 127, c = idx >> 7;
        wT[d*68 + c] = Wout[c*DI + d];
    }
    for (int idx = tid; idx < 64*CH; idx += 256) {
        int tok = idx >> 6, c = idx & 63;
        seqT[c*68 + tok] = g_seq[(size_t)(n0+tok)*CH + c];
    }
    __syncthreads();

    // correction + gating -> ysT[d][tok]
    for (int idx = tid; idx < 64*DI; idx += 256) {
        int tok = idx >> 7, d = idx & 127;
        size_t gi = (size_t)(n0+tok)*DI + d;
        float cdv = g_cd[gi];
        float y   = g_yl[gi];
        float xcv = g_xc[gi];
        float zv  = g_z[gi];
        if (chs[d] != 0.f) {
            float q = __expf(a0s[d] * cdv);
            float poly = Cs[tok*16 + 15] * Hs[d*17 + 15];
            #pragma unroll
            for (int s = 14; s >= 0; --s)
                poly = fmaf(q, poly, Cs[tok*16 + s] * Hs[d*17 + s]);
            y += q * poly;
        } else {
            #pragma unroll
            for (int s = 0; s < DS; ++s)
                y += Cs[tok*16 + s] * __expf(g_A[d*DS + s]*cdv) * Hs[d*17 + s];
        }
        ysT[d*68 + tok] = (y + xcv*dps[d]) * siluf(zv);
    }
    __syncthreads();

    // out_proj GEMM [64c x 64tok x 128K] + residual
    int cg = tid >> 4, tg = tid & 15;
    int c0 = cg*4, t0 = tg*4;
    float acc[4][4] = {};
    #pragma unroll 4
    for (int d = 0; d < DI; ++d) {
        float4 av = *(const float4*)&ysT[d*68 + t0];
        float4 wv = *(const float4*)&wT[d*68 + c0];
        acc[0][0] += wv.x*av.x; acc[0][1] += wv.x*av.y; acc[0][2] += wv.x*av.z; acc[0][3] += wv.x*av.w;
        acc[1][0] += wv.y*av.x; acc[1][1] += wv.y*av.y; acc[1][2] += wv.y*av.z; acc[1][3] += wv.y*av.w;
        acc[2][0] += wv.z*av.x; acc[2][1] += wv.z*av.y; acc[2][2] += wv.z*av.z; acc[2][3] += wv.z*av.w;
        acc[3][0] += wv.w*av.x; acc[3][1] += wv.w*av.y; acc[3][2] += wv.w*av.z; acc[3][3] += wv.w*av.w;
    }
    #pragma unroll
    for (int i = 0; i < 4; ++i)
        #pragma unroll
        for (int j = 0; j < 4; ++j) acc[i][j] += seqT[(c0+i)*68 + t0+j];
    __syncthreads();
    #pragma unroll
    for (int i = 0; i < 4; ++i)
        #pragma unroll
        for (int j = 0; j < 4; ++j) wT[(c0+i)*68 + t0+j] = acc[i][j];
    __syncthreads();
    for (int idx = tid; idx < CH*64; idx += 256) {
        int c = idx >> 6, tok = idx & 63;
        out[((size_t)(b*CH + c))*LSEQ + l0 + tok] = wT[c*68 + tok];
    }
}

// ---------------- launch --------------------------------------------------
extern "C" void kernel_launch(void* const* d_in, const int* in_sizes, int n_in,
                              void* d_out, int out_size) {
    const float* x       = (const float*)d_in[0];
    const float* dwh_w   = (const float*)d_in[1];
    const float* dwh_b   = (const float*)d_in[2];
    const float* dww_w   = (const float*)d_in[3];
    const float* dww_b   = (const float*)d_in[4];
    const float* conv_w  = (const float*)d_in[5];
    const float* conv_b  = (const float*)d_in[6];
    const float* bn_g    = (const float*)d_in[7];
    const float* bn_b    = (const float*)d_in[8];
    const float* bn_m    = (const float*)d_in[9];
    const float* bn_v    = (const float*)d_in[10];
    const float* ln_g    = (const float*)d_in[11];
    const float* ln_b    = (const float*)d_in[12];
    const float* in_proj = (const float*)d_in[13];
    const float* convd_w = (const float*)d_in[14];
    const float* convd_b = (const float*)d_in[15];
    const float* x_proj  = (const float*)d_in[16];
    const float* dt_w    = (const float*)d_in[17];
    const float* dt_b    = (const float*)d_in[18];
    const float* A_log   = (const float*)d_in[19];
    const float* Dp      = (const float*)d_in[20];
    const float* out_w   = (const float*)d_in[21];
    float* out = (float*)d_out;

    cudaFuncSetAttribute(k_fuse1, cudaFuncAttributeMaxDynamicSharedMemorySize, 69120);
    cudaFuncSetAttribute(k_fuse2, cudaFuncAttributeMaxDynamicSharedMemorySize, 78640);
    cudaFuncSetAttribute(k_fuse4, cudaFuncAttributeMaxDynamicSharedMemorySize, 101376);

    k_fuse1<<<BZ*HH, 256, 69120>>>(x, dwh_w, dwh_b, dww_w, dww_b, conv_w, conv_b,
                                   bn_g, bn_b, bn_m, bn_v, ln_g, ln_b, in_proj, A_log);
    k_fuse2<<<BZ*GCH, 256, 78640>>>(convd_w, convd_b, x_proj, dt_w, dt_b);
    k_comb<<<64, 128>>>();
    k_fuse4<<<BZ*GCH, 256, 101376>>>(Dp, out_w, out);
}